// round 11
// baseline (speedup 1.0000x reference)
#include <cuda_runtime.h>

#define NTOK 32768
#define NH 32
#define NCH 10                // float4 feature chunks per token (40 floats: 32 h + 2 label + 6 pad)
#define SLICE (NCH * NTOK)

// Feature slices: 0..9 obs inputs, 10..19 obs outputs, 20..21 pred ping-pong.
__device__ float4 g_ftr[22 * SLICE];

// Precomputed folded weights (padded to 40 where noted)
__device__ float g_M[40 * 40];     // (Wq^T Wk)/sqrt(34), [i][j], zero-padded
__device__ float g_kb[40];         // (Wk^T bq)/sqrt(34), zero-padded
__device__ float g_qb[40];         // (Wq^T bk)/sqrt(34), zero-padded
__device__ float g_cc[1];          // (bq.bk)/sqrt(34)
__device__ float g_cv[40][32];     // CV[j][k], rows 34..39 zero
__device__ float g_cb2[32];
__device__ float g_f2h[32][32];    // [i][k] = f2w[k][i] - colmean
__device__ float g_bh[32];

typedef unsigned long long u64;

__device__ __forceinline__ u64 pack2(float lo, float hi) {
    u64 r; asm("mov.b64 %0, {%1, %2};" : "=l"(r) : "f"(lo), "f"(hi)); return r;
}
__device__ __forceinline__ void unpack2(u64 v, float& lo, float& hi) {
    asm("mov.b64 {%0, %1}, %2;" : "=f"(lo), "=f"(hi) : "l"(v));
}
__device__ __forceinline__ u64 ffma2(u64 a, u64 b, u64 c) {
    u64 d; asm("fma.rn.f32x2 %0, %1, %2, %3;" : "=l"(d) : "l"(a), "l"(b), "l"(c)); return d;
}
__device__ __forceinline__ u64 fadd2(u64 a, u64 b) {
    u64 d; asm("add.rn.f32x2 %0, %1, %2;" : "=l"(d) : "l"(a), "l"(b)); return d;
}
__device__ __forceinline__ u64 fmul2(u64 a, u64 b) {
    u64 d; asm("mul.rn.f32x2 %0, %1, %2;" : "=l"(d) : "l"(a), "l"(b)); return d;
}

// ---------------------------------------------------------------------------
__global__ void __launch_bounds__(256) precomp_kernel(
    const float* __restrict__ ipw, const float* __restrict__ ipb,
    const float* __restrict__ opw, const float* __restrict__ opb,
    const float* __restrict__ saw, const float* __restrict__ sab,
    const float* __restrict__ f2w, const float* __restrict__ f2b)
{
    __shared__ float sCW[32][34];
    int tid = threadIdx.x;
    const float SC = 0.17149858514250882f;  // 1/sqrt(34)

    for (int idx = tid; idx < 40 * 40; idx += 256) {
        int i = idx / 40, j = idx % 40;
        float acc = 0.f;
        if (i < 34 && j < 34)
            for (int e = 0; e < 34; e++) acc += ipw[e * 34 + i] * ipw[(34 + e) * 34 + j];
        g_M[idx] = acc * SC;
    }
    for (int j = tid; j < 40; j += 256) {
        float a = 0.f, b = 0.f;
        if (j < 34)
            for (int e = 0; e < 34; e++) {
                a += ipb[e] * ipw[(34 + e) * 34 + j];
                b += ipw[e * 34 + j] * ipb[34 + e];
            }
        g_kb[j] = a * SC;
        g_qb[j] = b * SC;
    }
    if (tid == 0) {
        float c = 0.f;
        for (int e = 0; e < 34; e++) c += ipb[e] * ipb[34 + e];
        g_cc[0] = c * SC;
    }
    for (int idx = tid; idx < 32 * 34; idx += 256) {
        int k = idx / 34, i = idx % 34;
        float acc = 0.f;
        for (int t = 0; t < 34; t++) acc += saw[k * 34 + t] * opw[t * 34 + i];
        sCW[k][i] = acc;
    }
    __syncthreads();
    for (int idx = tid; idx < 40 * 32; idx += 256) {
        int j = idx / 32, k = idx % 32;
        float acc = 0.f;
        if (j < 34)
            for (int i = 0; i < 34; i++) acc += sCW[k][i] * ipw[(68 + i) * 34 + j];
        g_cv[j][k] = acc;
    }
    for (int k = tid; k < 32; k += 256) {
        float acc = sab[k];
        for (int t = 0; t < 34; t++) acc += saw[k * 34 + t] * opb[t];
        for (int i = 0; i < 34; i++) acc += sCW[k][i] * ipb[68 + i];
        g_cb2[k] = acc;
    }
    for (int idx = tid; idx < 32 * 32; idx += 256) {
        int i = idx / 32, k = idx % 32;
        float mu = 0.f;
        for (int kk = 0; kk < 32; kk++) mu += f2w[kk * 32 + i];
        g_f2h[i][k] = f2w[k * 32 + i] - mu * (1.f / 32.f);
    }
    for (int k = tid; k < 32; k += 256) {
        float mb = 0.f;
        for (int kk = 0; kk < 32; kk++) mb += f2b[kk];
        g_bh[k] = f2b[k] - mb * (1.f / 32.f);
    }
}

// ---------------------------------------------------------------------------
__global__ void __launch_bounds__(128) prep_kernel(const float* __restrict__ x)
{
    int n = blockIdx.x * 128 + threadIdx.x;
    int z = blockIdx.z;
    const float4* h4 = reinterpret_cast<const float4*>(x + ((size_t)z * NTOK + n) * NH);
    float4* o = g_ftr + (size_t)z * SLICE + n;
#pragma unroll
    for (int c = 0; c < 8; c++) o[(size_t)c * NTOK] = h4[c];
    int p = n & 4095;
    float4 lab;
    lab.x = (float)(p >> 6) * (1.f / 64.f);
    lab.y = (float)(p & 63) * (1.f / 64.f);
    lab.z = 0.f; lab.w = 0.f;
    o[(size_t)8 * NTOK] = lab;
    float4 zero = {0.f, 0.f, 0.f, 0.f};
    o[(size_t)9 * NTOK] = zero;
}

// neighbor offset for s (compile-time)
__device__ __forceinline__ constexpr int soff(int s) {
    return (s / 3 - 1) * 64 + (s % 3 - 1);
}

// ---------------------------------------------------------------------------
// One step, 2 threads/token as half-warp partners (lane ^ 16), branch-free,
// register-dieted: streamed center pass, derived neighbor addresses.
// ---------------------------------------------------------------------------
__global__ void __launch_bounds__(128, 3) step_kernel(
    int fin_slice, int fout_slice, float* __restrict__ outbase, int zmul,
    const float* __restrict__ lng, const float* __restrict__ lnb)
{
    __shared__ __align__(16) float sM[40][40];
    __shared__ __align__(16) float sCV[40][32];
    __shared__ __align__(16) float sF2[32][32];
    __shared__ __align__(16) float sKB[40];
    __shared__ __align__(16) float sQB[40];
    __shared__ __align__(16) float sCB2[32];
    __shared__ __align__(16) float sBH[32];
    __shared__ __align__(16) float sG[32];
    __shared__ __align__(16) float sBB[32];
    __shared__ float sCC;

    int tid = threadIdx.x;
    for (int idx = tid; idx < 40 * 40; idx += 128) sM[idx / 40][idx % 40] = g_M[idx];
    for (int idx = tid; idx < 40 * 32; idx += 128) sCV[idx / 32][idx % 32] = g_cv[idx / 32][idx % 32];
    for (int idx = tid; idx < 32 * 32; idx += 128) sF2[idx / 32][idx % 32] = g_f2h[idx / 32][idx % 32];
    if (tid < 40) { sKB[tid] = g_kb[tid]; sQB[tid] = g_qb[tid]; }
    if (tid < 32) {
        sCB2[tid] = g_cb2[tid]; sBH[tid] = g_bh[tid];
        sG[tid] = lng[tid];     sBB[tid] = lnb[tid];
    }
    if (tid == 0) sCC = g_cc[0];
    __syncthreads();

    int w = tid >> 5, lane = tid & 31;
    int hf = lane >> 4, sub = lane & 15;

    int z = blockIdx.z;
    const float4* fin = g_ftr + (size_t)(fin_slice + z * zmul) * SLICE;
    float4* fout      = g_ftr + (size_t)(fout_slice + z * zmul) * SLICE;
    float* out        = outbase + (size_t)z * zmul * NTOK * NH;

    int n = blockIdx.x * 64 + w * 16 + sub;
    int p = n & 4095;
    int row = p >> 6, col = p & 63;
    int rs = row + (row == 0) - (row == 63);
    int cs = col + (col == 0) - (col == 63);
    // center neighbor token (s=4); others derived by compile-time offsets
    int jt4 = (n >> 12) * 4096 + rs * 64 + cs;

    const int jf = 20 * hf;   // first owned a-row (float index)
    const int c0 = 5 * hf;    // first owned feature chunk

    // ---- pass A (streamed): a = own 20 rows of (M^T f4 + kb); full c4
    float c4 = sCC;
    u64 a[10];
#pragma unroll
    for (int t = 0; t < 10; t++) a[t] = *reinterpret_cast<const u64*>(&sKB[jf + 2 * t]);
    {
        const float4* cp = fin + jt4;
#pragma unroll
        for (int c = 0; c < 9; c++) {
            float4 v = cp[(size_t)c * NTOK];
            float fs[4] = {v.x, v.y, v.z, v.w};
#pragma unroll
            for (int j = 0; j < 4; j++) {
                int i = 4 * c + j;    // rows 34,35 of sM/sQB are zero
                c4 += fs[j] * sQB[i];
                u64 fp = pack2(fs[j], fs[j]);
#pragma unroll
                for (int t = 0; t < 10; t++)
                    a[t] = ffma2(fp, *reinterpret_cast<const u64*>(&sM[i][jf + 2 * t]), a[t]);
            }
        }
    }

    // ---- pass B: 9 partial scores over own chunks, combine via shfl(16)
    float e[9], l = 0.f;
    {
        const float4* kbase = fin + (size_t)c0 * NTOK + jt4;
#pragma unroll
        for (int s = 0; s < 9; s++) {
            const float4* kp = kbase + soff(s);
            u64 d0 = 0ull, d1 = 0ull;
#pragma unroll
            for (int cc = 0; cc < 5; cc++) {
                ulonglong2 v = *reinterpret_cast<const ulonglong2*>(&kp[(size_t)cc * NTOK]);
                d0 = ffma2(a[2 * cc], v.x, d0);
                d1 = ffma2(a[2 * cc + 1], v.y, d1);
            }
            u64 dd = fadd2(d0, d1);
            float x0, x1; unpack2(dd, x0, x1);
            float ps = x0 + x1;
            ps += __shfl_xor_sync(0xffffffffu, ps, 16);
            e[s] = __expf(ps + c4);
            l += e[s];
        }
    }
    float rl = 1.f / l;
#pragma unroll
    for (int s = 0; s < 9; s++) e[s] *= rl;

    // ---- pass C: fbar over own chunks (L1-hot reload)
    u64 fb[10];
#pragma unroll
    for (int t = 0; t < 10; t++) fb[t] = 0ull;
    {
        const float4* kbase = fin + (size_t)c0 * NTOK + jt4;
#pragma unroll
        for (int s = 0; s < 9; s++) {
            u64 ep = pack2(e[s], e[s]);
            const float4* fp4 = kbase + soff(s);
#pragma unroll
            for (int cc = 0; cc < 5; cc++) {
                ulonglong2 v = *reinterpret_cast<const ulonglong2*>(&fp4[(size_t)cc * NTOK]);
                fb[2 * cc]     = ffma2(ep, v.x, fb[2 * cc]);
                fb[2 * cc + 1] = ffma2(ep, v.y, fb[2 * cc + 1]);
            }
        }
    }

    // ---- z partial = 0.5*(h + cb2) + CV[own j] @ fbar_own; combine via shfl
    const u64 HALF = pack2(0.5f, 0.5f);
    u64 zacc[16];
#pragma unroll
    for (int c = 0; c < 8; c++) {
        ulonglong2 hv = *reinterpret_cast<const ulonglong2*>(&fin[(size_t)c * NTOK + n]);
        u64 b0 = *reinterpret_cast<const u64*>(&sCB2[4 * c]);
        u64 b1 = *reinterpret_cast<const u64*>(&sCB2[4 * c + 2]);
        zacc[2 * c]     = fmul2(HALF, fadd2(hv.x, b0));
        zacc[2 * c + 1] = fmul2(HALF, fadd2(hv.y, b1));
    }
#pragma unroll
    for (int t = 0; t < 10; t++) {          // unpack fb transiently, 2 j per t
        float f0, f1; unpack2(fb[t], f0, f1);
        u64 fp0 = pack2(f0, f0), fp1 = pack2(f1, f1);
        const float* r0 = sCV[jf + 2 * t];
        const float* r1 = sCV[jf + 2 * t + 1];
#pragma unroll
        for (int k = 0; k < 16; k++)
            zacc[k] = ffma2(fp0, *reinterpret_cast<const u64*>(&r0[2 * k]), zacc[k]);
#pragma unroll
        for (int k = 0; k < 16; k++)
            zacc[k] = ffma2(fp1, *reinterpret_cast<const u64*>(&r1[2 * k]), zacc[k]);
    }
#pragma unroll
    for (int t = 0; t < 16; t++) {
        u64 other = __shfl_xor_sync(0xffffffffu, zacc[t], 16);
        zacc[t] = fadd2(zacc[t], other);
    }

    // ---- v partial = 0.5*bh + F2[own i] @ z_own; combine via shfl
    u64 vacc[16];
#pragma unroll
    for (int t = 0; t < 16; t++)
        vacc[t] = fmul2(HALF, *reinterpret_cast<const u64*>(&sBH[2 * t]));
#pragma unroll
    for (int t = 0; t < 8; t++) {           // own z floats [16hf, 16hf+16)
        float z0, z1; unpack2(zacc[8 * hf + t], z0, z1);
        u64 zp0 = pack2(z0, z0), zp1 = pack2(z1, z1);
        const float* r0 = sF2[16 * hf + 2 * t];
        const float* r1 = sF2[16 * hf + 2 * t + 1];
#pragma unroll
        for (int k = 0; k < 16; k++)
            vacc[k] = ffma2(zp0, *reinterpret_cast<const u64*>(&r0[2 * k]), vacc[k]);
#pragma unroll
        for (int k = 0; k < 16; k++)
            vacc[k] = ffma2(zp1, *reinterpret_cast<const u64*>(&r1[2 * k]), vacc[k]);
    }
#pragma unroll
    for (int t = 0; t < 16; t++) {
        u64 other = __shfl_xor_sync(0xffffffffu, vacc[t], 16);
        vacc[t] = fadd2(vacc[t], other);
    }

    // ---- layernorm (mean folded): var = sum v^2, packed
    u64 varp = 0ull;
#pragma unroll
    for (int t = 0; t < 16; t++) varp = ffma2(vacc[t], vacc[t], varp);
    float v0, v1; unpack2(varp, v0, v1);
    float r = rsqrtf((v0 + v1) * (1.f / 32.f) + 1e-5f);
    u64 rp = pack2(r, r);

    // ---- own output chunks [4hf, 4hf+4)
    float4* orow = reinterpret_cast<float4*>(out + (size_t)n * NH);
#pragma unroll
    for (int cc = 0; cc < 4; cc++) {
        int kof = 16 * hf + 4 * cc;
        u64 y0 = ffma2(fmul2(vacc[8 * hf + 2 * cc], rp),
                       *reinterpret_cast<const u64*>(&sG[kof]),
                       *reinterpret_cast<const u64*>(&sBB[kof]));
        u64 y1 = ffma2(fmul2(vacc[8 * hf + 2 * cc + 1], rp),
                       *reinterpret_cast<const u64*>(&sG[kof + 2]),
                       *reinterpret_cast<const u64*>(&sBB[kof + 2]));
        ulonglong2 y; y.x = y0; y.y = y1;
        float4 yf = *reinterpret_cast<float4*>(&y);
        orow[4 * hf + cc] = yf;
        fout[(size_t)(4 * hf + cc) * NTOK + n] = yf;
    }
    // chunk 8 (label, hf=0) / chunk 9 (zeros, hf=1) — branch-free select
    float sel = (hf == 0) ? 1.f : 0.f;
    float4 tailv;
    tailv.x = sel * ((float)row * (1.f / 64.f));
    tailv.y = sel * ((float)col * (1.f / 64.f));
    tailv.z = 0.f; tailv.w = 0.f;
    fout[(size_t)(8 + hf) * NTOK + n] = tailv;
}

// ---------------------------------------------------------------------------
extern "C" void kernel_launch(void* const* d_in, const int* in_sizes, int n_in,
                              void* d_out, int out_size)
{
    const float* x   = (const float*)d_in[0];
    const float* ipw = (const float*)d_in[1];
    const float* ipb = (const float*)d_in[2];
    const float* opw = (const float*)d_in[3];
    const float* opb = (const float*)d_in[4];
    const float* saw = (const float*)d_in[5];
    const float* sab = (const float*)d_in[6];
    const float* f2w = (const float*)d_in[7];
    const float* f2b = (const float*)d_in[8];
    const float* lng = (const float*)d_in[9];
    const float* lnb = (const float*)d_in[10];
    float* out = (float*)d_out;

    precomp_kernel<<<1, 256>>>(ipw, ipb, opw, opb, saw, sab, f2w, f2b);

    prep_kernel<<<dim3(NTOK / 128, 1, 10), 128>>>(x);

    const int NB = NTOK / 64;   // 512 blocks of 128 threads (2 threads/token)

    // Observation: slices 0..9 -> 10..19, output rows 0..9
    step_kernel<<<dim3(NB, 1, 10), 128>>>(0, 10, out, 1, lng, lnb);

    // Prediction: 50 sequential steps; slice 19 seeds ping-pong 20/21
    for (int i = 0; i < 50; i++) {
        int fin = (i == 0) ? 19 : 20 + ((i - 1) & 1);
        int fot = 20 + (i & 1);
        float* o = out + (size_t)(10 + i) * NTOK * NH;
        step_kernel<<<dim3(NB, 1, 1), 128>>>(fin, fot, o, 0, lng, lnb);
    }
}

// round 13
// speedup vs baseline: 2.3278x; 2.3278x over previous
#include <cuda_runtime.h>

#define NTOK 32768
#define NH 32
#define NCH 9                 // float4 feature chunks per token (36 floats)
#define SLICE (NCH * NTOK)

// Feature slices: 0..9 obs inputs, 10..19 obs outputs, 20..21 pred ping-pong.
__device__ float4 g_ftr[22 * SLICE];

// Precomputed folded weights
__device__ float g_M[36 * 36];     // (Wq^T Wk)/sqrt(34), [i][j], zero-padded
__device__ float g_kb[36];
__device__ float g_qb[36];
__device__ float g_cc[1];
__device__ float g_cv[36][32];     // CV[j][k]
__device__ float g_cb2[32];
__device__ float g_f2h[32][32];    // [i][k] = f2w[k][i] - colmean
__device__ float g_bh[32];
__device__ int   g_flag[256];      // per-block step counters (pred)

typedef unsigned long long u64;

__device__ __forceinline__ u64 pack2(float lo, float hi) {
    u64 r; asm("mov.b64 %0, {%1, %2};" : "=l"(r) : "f"(lo), "f"(hi)); return r;
}
__device__ __forceinline__ void unpack2(u64 v, float& lo, float& hi) {
    asm("mov.b64 {%0, %1}, %2;" : "=f"(lo), "=f"(hi) : "l"(v));
}
__device__ __forceinline__ u64 ffma2(u64 a, u64 b, u64 c) {
    u64 d; asm("fma.rn.f32x2 %0, %1, %2, %3;" : "=l"(d) : "l"(a), "l"(b), "l"(c)); return d;
}
__device__ __forceinline__ u64 fadd2(u64 a, u64 b) {
    u64 d; asm("add.rn.f32x2 %0, %1, %2;" : "=l"(d) : "l"(a), "l"(b)); return d;
}
__device__ __forceinline__ u64 fmul2(u64 a, u64 b) {
    u64 d; asm("mul.rn.f32x2 %0, %1, %2;" : "=l"(d) : "l"(a), "l"(b)); return d;
}

// ---------------------------------------------------------------------------
__global__ void __launch_bounds__(256) precomp_kernel(
    const float* __restrict__ ipw, const float* __restrict__ ipb,
    const float* __restrict__ opw, const float* __restrict__ opb,
    const float* __restrict__ saw, const float* __restrict__ sab,
    const float* __restrict__ f2w, const float* __restrict__ f2b)
{
    __shared__ float sCW[32][34];
    int tid = threadIdx.x;
    const float SC = 0.17149858514250882f;  // 1/sqrt(34)

    for (int idx = tid; idx < 36 * 36; idx += 256) {
        int i = idx / 36, j = idx % 36;
        float acc = 0.f;
        if (i < 34 && j < 34)
            for (int e = 0; e < 34; e++) acc += ipw[e * 34 + i] * ipw[(34 + e) * 34 + j];
        g_M[idx] = acc * SC;
    }
    for (int j = tid; j < 36; j += 256) {
        float a = 0.f, b = 0.f;
        if (j < 34)
            for (int e = 0; e < 34; e++) {
                a += ipb[e] * ipw[(34 + e) * 34 + j];
                b += ipw[e * 34 + j] * ipb[34 + e];
            }
        g_kb[j] = a * SC;
        g_qb[j] = b * SC;
    }
    if (tid == 0) {
        float c = 0.f;
        for (int e = 0; e < 34; e++) c += ipb[e] * ipb[34 + e];
        g_cc[0] = c * SC;
    }
    for (int idx = tid; idx < 32 * 34; idx += 256) {
        int k = idx / 34, i = idx % 34;
        float acc = 0.f;
        for (int t = 0; t < 34; t++) acc += saw[k * 34 + t] * opw[t * 34 + i];
        sCW[k][i] = acc;
    }
    __syncthreads();
    for (int idx = tid; idx < 36 * 32; idx += 256) {
        int j = idx / 32, k = idx % 32;
        float acc = 0.f;
        if (j < 34)
            for (int i = 0; i < 34; i++) acc += sCW[k][i] * ipw[(68 + i) * 34 + j];
        g_cv[j][k] = acc;
    }
    for (int k = tid; k < 32; k += 256) {
        float acc = sab[k];
        for (int t = 0; t < 34; t++) acc += saw[k * 34 + t] * opb[t];
        for (int i = 0; i < 34; i++) acc += sCW[k][i] * ipb[68 + i];
        g_cb2[k] = acc;
    }
    for (int idx = tid; idx < 32 * 32; idx += 256) {
        int i = idx / 32, k = idx % 32;
        float mu = 0.f;
        for (int kk = 0; kk < 32; kk++) mu += f2w[kk * 32 + i];
        g_f2h[i][k] = f2w[k * 32 + i] - mu * (1.f / 32.f);
    }
    for (int k = tid; k < 32; k += 256) {
        float mb = 0.f;
        for (int kk = 0; kk < 32; kk++) mb += f2b[kk];
        g_bh[k] = f2b[k] - mb * (1.f / 32.f);
    }
}

// ---------------------------------------------------------------------------
__global__ void __launch_bounds__(128) prep_kernel(const float* __restrict__ x)
{
    int tid = threadIdx.x;
    int n = blockIdx.x * 128 + tid;
    int z = blockIdx.z;
    const float4* h4 = reinterpret_cast<const float4*>(x + ((size_t)z * NTOK + n) * NH);
    float4* o = g_ftr + (size_t)z * SLICE + n;
#pragma unroll
    for (int c = 0; c < 8; c++) o[(size_t)c * NTOK] = h4[c];
    int p = n & 4095;
    float4 lab;
    lab.x = (float)(p >> 6) * (1.f / 64.f);
    lab.y = (float)(p & 63) * (1.f / 64.f);
    lab.z = 0.f; lab.w = 0.f;
    o[(size_t)8 * NTOK] = lab;
    if (z == 0 && blockIdx.x == 0) {       // reset pred flags each launch
        g_flag[tid] = 0;
        g_flag[tid + 128] = 0;
    }
}

// ---------------------------------------------------------------------------
// Shared-memory weight block (all arrays 16B-aligned by construction)
// ---------------------------------------------------------------------------
struct __align__(16) SW {
    float M[36][36];    // 5184 B
    float CV[36][32];   // 4608 B
    float F2[32][32];   // 4096 B
    float KB[36], QB[36];
    float CB2[32], BH[32], G[32], BB[32];
    float CC;
};

__device__ __forceinline__ void stage_weights(SW& s, int tid,
        const float* __restrict__ lng, const float* __restrict__ lnb)
{
    for (int idx = tid; idx < 36 * 36; idx += 128) s.M[idx / 36][idx % 36] = g_M[idx];
    for (int idx = tid; idx < 36 * 32; idx += 128) s.CV[idx / 32][idx % 32] = g_cv[idx / 32][idx % 32];
    for (int idx = tid; idx < 32 * 32; idx += 128) s.F2[idx / 32][idx % 32] = g_f2h[idx / 32][idx % 32];
    if (tid < 36) { s.KB[tid] = g_kb[tid]; s.QB[tid] = g_qb[tid]; }
    if (tid < 32) {
        s.CB2[tid] = g_cb2[tid]; s.BH[tid] = g_bh[tid];
        s.G[tid] = lng[tid];     s.BB[tid] = lnb[tid];
    }
    if (tid == 0) s.CC = g_cc[0];
}

// ---------------------------------------------------------------------------
// One token's full step (R5 body + LDS.128 weight loads)
// ---------------------------------------------------------------------------
__device__ __forceinline__ void do_token(const SW& s,
    const float4* __restrict__ fin, float4* __restrict__ fout,
    float* __restrict__ orow, int n, const int* jt, int row, int col)
{
    // pass A: a = M^T f4 + kb ; c4 = qb.f4 + cc
    float f4f[36];
#pragma unroll
    for (int c = 0; c < 9; c++) {
        float4 v = fin[(size_t)c * NTOK + jt[4]];
        f4f[4 * c + 0] = v.x; f4f[4 * c + 1] = v.y;
        f4f[4 * c + 2] = v.z; f4f[4 * c + 3] = v.w;
    }
    float c4 = s.CC;
#pragma unroll
    for (int i = 0; i < 34; i++) c4 += f4f[i] * s.QB[i];

    u64 a[18];
#pragma unroll
    for (int t = 0; t < 9; t++) {
        ulonglong2 kb = *reinterpret_cast<const ulonglong2*>(&s.KB[4 * t]);
        a[2 * t] = kb.x; a[2 * t + 1] = kb.y;
    }
#pragma unroll
    for (int i = 0; i < 34; i++) {
        u64 fp = pack2(f4f[i], f4f[i]);
#pragma unroll
        for (int t = 0; t < 9; t++) {
            ulonglong2 w = *reinterpret_cast<const ulonglong2*>(&s.M[i][4 * t]);
            a[2 * t]     = ffma2(fp, w.x, a[2 * t]);
            a[2 * t + 1] = ffma2(fp, w.y, a[2 * t + 1]);
        }
    }

    // online softmax over 9 neighbors accumulating fbar
    u64 fb[18];
#pragma unroll
    for (int t = 0; t < 18; t++) fb[t] = 0ull;
    float m = -1e30f, l = 0.f;
#pragma unroll
    for (int sx = 0; sx < 9; sx++) {
        const float4* fp4 = fin + jt[sx];
        u64 fs[18];
#pragma unroll
        for (int c = 0; c < 9; c++) {
            ulonglong2 v = *reinterpret_cast<const ulonglong2*>(&fp4[(size_t)c * NTOK]);
            fs[2 * c] = v.x; fs[2 * c + 1] = v.y;
        }
        u64 d0 = 0ull, d1 = 0ull;
#pragma unroll
        for (int t = 0; t < 9; t++) {
            d0 = ffma2(a[2 * t], fs[2 * t], d0);
            d1 = ffma2(a[2 * t + 1], fs[2 * t + 1], d1);
        }
        float x0, x1, x2, x3;
        unpack2(d0, x0, x1); unpack2(d1, x2, x3);
        float sc = (x0 + x1) + (x2 + x3) + c4;
        float m2 = fmaxf(m, sc);
        float cold = __expf(m - m2);
        float e = __expf(sc - m2);
        l = l * cold + e;
        u64 cp = pack2(cold, cold), ep = pack2(e, e);
#pragma unroll
        for (int t = 0; t < 18; t++)
            fb[t] = ffma2(ep, fs[t], fmul2(fb[t], cp));
        m = m2;
    }
    float rl = 1.f / l;
    u64 rlp = pack2(rl, rl);

    // z = h + CV @ fbar + cb2
    u64 zacc[16];
#pragma unroll
    for (int t = 0; t < 8; t++) {
        ulonglong2 bb = *reinterpret_cast<const ulonglong2*>(&s.CB2[4 * t]);
        zacc[2 * t] = bb.x; zacc[2 * t + 1] = bb.y;
    }
#pragma unroll
    for (int c = 0; c < 8; c++) {
        ulonglong2 hv = *reinterpret_cast<const ulonglong2*>(&fin[(size_t)c * NTOK + n]);
        zacc[2 * c]     = fadd2(zacc[2 * c], hv.x);
        zacc[2 * c + 1] = fadd2(zacc[2 * c + 1], hv.y);
    }
#pragma unroll
    for (int t = 0; t < 17; t++) {   // j = 2t, 2t+1 (0..33)
        u64 fbn = fmul2(fb[t], rlp);
        float f0, f1; unpack2(fbn, f0, f1);
        u64 fp0 = pack2(f0, f0), fp1 = pack2(f1, f1);
#pragma unroll
        for (int k = 0; k < 8; k++) {
            ulonglong2 w = *reinterpret_cast<const ulonglong2*>(&s.CV[2 * t][4 * k]);
            zacc[2 * k]     = ffma2(fp0, w.x, zacc[2 * k]);
            zacc[2 * k + 1] = ffma2(fp0, w.y, zacc[2 * k + 1]);
        }
#pragma unroll
        for (int k = 0; k < 8; k++) {
            ulonglong2 w = *reinterpret_cast<const ulonglong2*>(&s.CV[2 * t + 1][4 * k]);
            zacc[2 * k]     = ffma2(fp1, w.x, zacc[2 * k]);
            zacc[2 * k + 1] = ffma2(fp1, w.y, zacc[2 * k + 1]);
        }
    }

    // v = F2h @ z + bh
    u64 vacc[16];
#pragma unroll
    for (int t = 0; t < 8; t++) {
        ulonglong2 bb = *reinterpret_cast<const ulonglong2*>(&s.BH[4 * t]);
        vacc[2 * t] = bb.x; vacc[2 * t + 1] = bb.y;
    }
#pragma unroll
    for (int t = 0; t < 16; t++) {   // i = 2t, 2t+1
        float z0, z1; unpack2(zacc[t], z0, z1);
        u64 zp0 = pack2(z0, z0), zp1 = pack2(z1, z1);
#pragma unroll
        for (int k = 0; k < 8; k++) {
            ulonglong2 w = *reinterpret_cast<const ulonglong2*>(&s.F2[2 * t][4 * k]);
            vacc[2 * k]     = ffma2(zp0, w.x, vacc[2 * k]);
            vacc[2 * k + 1] = ffma2(zp0, w.y, vacc[2 * k + 1]);
        }
#pragma unroll
        for (int k = 0; k < 8; k++) {
            ulonglong2 w = *reinterpret_cast<const ulonglong2*>(&s.F2[2 * t + 1][4 * k]);
            vacc[2 * k]     = ffma2(zp1, w.x, vacc[2 * k]);
            vacc[2 * k + 1] = ffma2(zp1, w.y, vacc[2 * k + 1]);
        }
    }

    // layernorm (mean folded out): var = sum v^2, packed
    u64 varp = 0ull;
#pragma unroll
    for (int t = 0; t < 16; t++) varp = ffma2(vacc[t], vacc[t], varp);
    float v0, v1; unpack2(varp, v0, v1);
    float r = rsqrtf((v0 + v1) * (1.f / 32.f) + 1e-5f);
    u64 rp = pack2(r, r);

    float4* o4 = reinterpret_cast<float4*>(orow);
#pragma unroll
    for (int c = 0; c < 8; c++) {
        u64 y0 = ffma2(fmul2(vacc[2 * c], rp),
                       *reinterpret_cast<const u64*>(&s.G[4 * c]),
                       *reinterpret_cast<const u64*>(&s.BB[4 * c]));
        u64 y1 = ffma2(fmul2(vacc[2 * c + 1], rp),
                       *reinterpret_cast<const u64*>(&s.G[4 * c + 2]),
                       *reinterpret_cast<const u64*>(&s.BB[4 * c + 2]));
        ulonglong2 y; y.x = y0; y.y = y1;
        float4 yf = *reinterpret_cast<float4*>(&y);
        o4[c] = yf;
        fout[(size_t)c * NTOK + n] = yf;
    }
    float4 lab;
    lab.x = (float)row * (1.f / 64.f);
    lab.y = (float)col * (1.f / 64.f);
    lab.z = 0.f; lab.w = 0.f;
    fout[(size_t)8 * NTOK + n] = lab;
}

// ---------------------------------------------------------------------------
// Observation: 10 independent steps, batched over grid.z.
// ---------------------------------------------------------------------------
__global__ void __launch_bounds__(128) obs_kernel(
    float* __restrict__ out,
    const float* __restrict__ lng, const float* __restrict__ lnb)
{
    __shared__ SW s;
    int tid = threadIdx.x;
    stage_weights(s, tid, lng, lnb);
    __syncthreads();

    int z = blockIdx.z;
    const float4* fin = g_ftr + (size_t)z * SLICE;
    float4* fout      = g_ftr + (size_t)(10 + z) * SLICE;

    int n = blockIdx.x * 128 + tid;
    int p = n & 4095;
    int row = p >> 6, col = p & 63;
    int rs = row + (row == 0) - (row == 63);
    int cs = col + (col == 0) - (col == 63);
    int jb = (n >> 12) * 4096;
    int jt[9];
#pragma unroll
    for (int sx = 0; sx < 9; sx++)
        jt[sx] = jb + (rs + sx / 3 - 1) * 64 + (cs + sx % 3 - 1);

    do_token(s, fin, fout, out + ((size_t)z * NTOK + n) * NH, n, jt, row, col);
}

// ---------------------------------------------------------------------------
// Prediction: persistent kernel, all 50 sequential steps in one launch.
// 256 co-resident blocks; block b depends only on blocks b±1 (same batch).
// ---------------------------------------------------------------------------
__global__ void __launch_bounds__(128) pred_kernel(
    float* __restrict__ out,
    const float* __restrict__ lng, const float* __restrict__ lnb)
{
    __shared__ SW s;
    int tid = threadIdx.x;
    stage_weights(s, tid, lng, lnb);
    __syncthreads();

    int b = blockIdx.x;
    int pos = b & 31;                 // block index within its batch (32 blocks/batch)
    int n = b * 128 + tid;
    int p = n & 4095;
    int row = p >> 6, col = p & 63;
    int rs = row + (row == 0) - (row == 63);
    int cs = col + (col == 0) - (col == 63);
    int jb = (n >> 12) * 4096;
    int jt[9];
#pragma unroll
    for (int sx = 0; sx < 9; sx++)
        jt[sx] = jb + (rs + sx / 3 - 1) * 64 + (cs + sx % 3 - 1);

    for (int i = 0; i < 50; i++) {
        const float4* fin = g_ftr + (size_t)(i == 0 ? 19 : 20 + ((i - 1) & 1)) * SLICE;
        float4* fout      = g_ftr + (size_t)(20 + (i & 1)) * SLICE;
        float* orow       = out + ((size_t)(10 + i) * NTOK + n) * NH;

        do_token(s, fin, fout, orow, n, jt, row, col);

        // release: order all my stores (and flush L1 so next step's neighbor
        // reads can't hit stale lines), then publish progress
        __threadfence();
        __syncthreads();
        if (tid == 0) {
            atomicExch(&g_flag[b], i + 1);
            if (pos > 0)  while (atomicAdd(&g_flag[b - 1], 0) <= i) { }
            if (pos < 31) while (atomicAdd(&g_flag[b + 1], 0) <= i) { }
        }
        __syncthreads();
    }
}

// ---------------------------------------------------------------------------
extern "C" void kernel_launch(void* const* d_in, const int* in_sizes, int n_in,
                              void* d_out, int out_size)
{
    const float* x   = (const float*)d_in[0];
    const float* ipw = (const float*)d_in[1];
    const float* ipb = (const float*)d_in[2];
    const float* opw = (const float*)d_in[3];
    const float* opb = (const float*)d_in[4];
    const float* saw = (const float*)d_in[5];
    const float* sab = (const float*)d_in[6];
    const float* f2w = (const float*)d_in[7];
    const float* f2b = (const float*)d_in[8];
    const float* lng = (const float*)d_in[9];
    const float* lnb = (const float*)d_in[10];
    float* out = (float*)d_out;

    precomp_kernel<<<1, 256>>>(ipw, ipb, opw, opb, saw, sab, f2w, f2b);

    prep_kernel<<<dim3(NTOK / 128, 1, 10), 128>>>(x);

    // Observation: slices 0..9 -> 10..19, output rows 0..9
    obs_kernel<<<dim3(NTOK / 128, 1, 10), 128>>>(out, lng, lnb);

    // Prediction: one persistent launch, 50 sequential steps
    pred_kernel<<<dim3(256, 1, 1), 128>>>(out, lng, lnb);
}